// round 5
// baseline (speedup 1.0000x reference)
#include <cuda_runtime.h>
#include <math_constants.h>

#define SEQ 1024
#define BSZ 8
#define EMBED 512
#define NH 8
#define QHD 32
#define PD 4
#define IN_PROJ 544

// Scratch for projected q/k/p, laid out [b][h][s][d] so kernel 2 streams contiguously.
__device__ float g_Q[BSZ * NH * SEQ * QHD];   // 8 MB
__device__ float g_K[BSZ * NH * SEQ * QHD];   // 8 MB
__device__ float g_P[BSZ * NH * SEQ * PD];    // 1 MB

// ---------------------------------------------------------------------------
// Kernel 1: xp = x @ W^T + b, scattered into g_Q / g_K / g_P.
// (Round-1 version, ~150us — at scalar FFMA floor.)
// ---------------------------------------------------------------------------
__global__ __launch_bounds__(256) void proj_kernel(
    const float* __restrict__ x, const float* __restrict__ W,
    const float* __restrict__ bias)
{
    __shared__ float As[16][64];
    __shared__ float Bs[16][64];

    const int tid = threadIdx.x;
    const int m0 = blockIdx.y * 64;
    const int n0 = blockIdx.x * 64;
    const int tx = tid & 15;
    const int ty = tid >> 4;
    const int lr = tid >> 2;
    const int lc = (tid & 3) * 4;

    float acc[4][4];
#pragma unroll
    for (int i = 0; i < 4; i++)
#pragma unroll
        for (int j = 0; j < 4; j++) acc[i][j] = 0.f;

    for (int k0 = 0; k0 < EMBED; k0 += 16) {
        float4 av = *(const float4*)&x[(size_t)(m0 + lr) * EMBED + k0 + lc];
        float4 bv = make_float4(0.f, 0.f, 0.f, 0.f);
        if (n0 + lr < IN_PROJ)
            bv = *(const float4*)&W[(size_t)(n0 + lr) * EMBED + k0 + lc];
        As[lc + 0][lr] = av.x; As[lc + 1][lr] = av.y;
        As[lc + 2][lr] = av.z; As[lc + 3][lr] = av.w;
        Bs[lc + 0][lr] = bv.x; Bs[lc + 1][lr] = bv.y;
        Bs[lc + 2][lr] = bv.z; Bs[lc + 3][lr] = bv.w;
        __syncthreads();
#pragma unroll
        for (int k = 0; k < 16; k++) {
            float4 a = *(const float4*)&As[k][ty * 4];
            float4 b = *(const float4*)&Bs[k][tx * 4];
            float aa[4] = {a.x, a.y, a.z, a.w};
            float bb[4] = {b.x, b.y, b.z, b.w};
#pragma unroll
            for (int i = 0; i < 4; i++)
#pragma unroll
                for (int j = 0; j < 4; j++) acc[i][j] += aa[i] * bb[j];
        }
        __syncthreads();
    }

#pragma unroll
    for (int i = 0; i < 4; i++) {
        const int m = m0 + ty * 4 + i;
        const int s = m >> 3;
        const int bb = m & 7;
#pragma unroll
        for (int j = 0; j < 4; j++) {
            const int n = n0 + tx * 4 + j;
            if (n >= IN_PROJ) continue;
            const float v = acc[i][j] + bias[n];
            if (n < 256) {
                const int h = n >> 5, d = n & 31;
                g_Q[(((size_t)(bb * NH + h)) * SEQ + s) * QHD + d] = v;
            } else if (n < 512) {
                const int g = n - 256;
                const int h = g >> 5, d = g & 31;
                g_K[(((size_t)(bb * NH + h)) * SEQ + s) * QHD + d] = v;
            } else {
                const int g = n - 512;
                const int h = g >> 2, d = g & 3;
                g_P[(((size_t)(bb * NH + h)) * SEQ + s) * PD + d] = v;
            }
        }
    }
}

// ---------------------------------------------------------------------------
// Kernel 2: scores in registers; thread tile = 4 t-rows x 8 s-values.
// CTA = (b, h, 16 t-rows). 256 threads: tg = tid>>6 -> 4 rows, cl = tid&63.
// SC=512 K chunk in SMEM (74KB), 2 chunks. 2 CTAs/SM.
// ---------------------------------------------------------------------------
#define TT 16
#define SC 512
#define KP 36    // K row pitch (floats): 8-lane LDS.128 phases conflict-free
#define NCH (SEQ / SC)   // 2

#define KS_FLOATS (SC * KP)                 // 18432
#define QS_OFF KS_FLOATS                    // Qs: TT*QHD = 512
#define PS_OFF (QS_OFF + TT * QHD)          // Ps: TT*4
#define RED_OFF (PS_OFF + TT * PD)          // red: TT*2
#define SM_FLOATS (RED_OFF + TT * 2)        // 19040 floats = 76160 B

__global__ __launch_bounds__(256, 2) void attn_kernel(
    const float* __restrict__ pos, const float* __restrict__ off,
    float* __restrict__ out)
{
    extern __shared__ float sm[];
    float* Ks = sm;
    float* Qs = sm + QS_OFF;
    float4* Ps = (float4*)(sm + PS_OFF);
    float* red = sm + RED_OFF;              // [TT][2]

    const int tid = threadIdx.x;
    const int t0 = blockIdx.x * TT;
    const int h = blockIdx.y;
    const int b = blockIdx.z;

    const float* Qg = g_Q + ((size_t)(b * NH + h)) * SEQ * QHD;
    const float* Kg = g_K + ((size_t)(b * NH + h)) * SEQ * QHD;
    const float* Pg = g_P + ((size_t)(b * NH + h)) * SEQ * PD;

    // Stage Q tile (16x32) and P vectors once.
    if (tid < 128) {
        const int r = tid >> 3, d4 = tid & 7;
        *(float4*)&Qs[r * QHD + d4 * 4] =
            *(const float4*)&Qg[(size_t)(t0 + r) * QHD + d4 * 4];
    }
    if (tid < TT)
        Ps[tid] = *(const float4*)&Pg[(size_t)(t0 + tid) * PD];

    const int cl = tid & 63;     // s-lane; s = c*SC + j*64 + cl
    const int tg = tid >> 6;     // 0..3 -> rows tg*4 .. tg*4+3
    const float* qrow = Qs + (tg * 4) * QHD;

    float sc_[4][NCH][8];        // [row][chunk][j]

#pragma unroll
    for (int c = 0; c < NCH; c++) {
        __syncthreads();         // K buffer reuse (and Q/P staging on c==0)
        // stage K chunk: 512 rows x 8 float4 over 256 threads -> 16 each
#pragma unroll
        for (int i = 0; i < (SC * 8) / 256; i++) {
            const int idx = tid + i * 256;
            const int s = idx >> 3, d4 = idx & 7;
            *(float4*)&Ks[s * KP + d4 * 4] =
                *(const float4*)&Kg[(size_t)(c * SC + s) * QHD + d4 * 4];
        }
        __syncthreads();

#pragma unroll
        for (int r = 0; r < 4; r++)
#pragma unroll
            for (int j = 0; j < 8; j++) sc_[r][c][j] = 0.f;

#pragma unroll
        for (int d4 = 0; d4 < 8; d4++) {
            float4 q4[4];
#pragma unroll
            for (int r = 0; r < 4; r++)
                q4[r] = *(const float4*)&qrow[r * QHD + d4 * 4];
#pragma unroll
            for (int j = 0; j < 8; j++) {
                const float4 k4 = *(const float4*)&Ks[(cl + j * 64) * KP + d4 * 4];
#pragma unroll
                for (int r = 0; r < 4; r++) {
                    sc_[r][c][j] += q4[r].x * k4.x + q4[r].y * k4.y +
                                    q4[r].z * k4.z + q4[r].w * k4.w;
                }
            }
        }

        // epilogue: + pos + offset
#pragma unroll
        for (int r = 0; r < 4; r++) {
            const int tglob = t0 + tg * 4 + r;
            const float4 p = Ps[tg * 4 + r];
#pragma unroll
            for (int j = 0; j < 8; j++) {
                const int s = c * SC + j * 64 + cl;
                const float4 pe = *(const float4*)&pos[((size_t)tglob * SEQ + s) * PD];
                const float o = off[((size_t)b * SEQ + tglob) * SEQ + s];
                sc_[r][c][j] += p.x * pe.x + p.y * pe.y + p.z * pe.z + p.w * pe.w + o;
            }
        }
    }

    // ------------------- softmax (row owned by 64 lanes = 2 warps) ---------
    const int lane = tid & 31;
    const int w2 = (tid >> 5) & 1;

    float m[4];
#pragma unroll
    for (int r = 0; r < 4; r++) {
        float v = -CUDART_INF_F;
#pragma unroll
        for (int c = 0; c < NCH; c++)
#pragma unroll
            for (int j = 0; j < 8; j++) v = fmaxf(v, sc_[r][c][j]);
#pragma unroll
        for (int o_ = 16; o_ > 0; o_ >>= 1)
            v = fmaxf(v, __shfl_xor_sync(0xffffffffu, v, o_));
        m[r] = v;
    }
    __syncthreads();
    if (lane == 0) {
#pragma unroll
        for (int r = 0; r < 4; r++) red[(tg * 4 + r) * 2 + w2] = m[r];
    }
    __syncthreads();
#pragma unroll
    for (int r = 0; r < 4; r++) {
        const int row = tg * 4 + r;
        m[r] = fmaxf(red[row * 2 + 0], red[row * 2 + 1]);
    }
    __syncthreads();

    float sum[4];
#pragma unroll
    for (int r = 0; r < 4; r++) {
        float s_ = 0.f;
#pragma unroll
        for (int c = 0; c < NCH; c++)
#pragma unroll
            for (int j = 0; j < 8; j++) {
                const float e = __expf(sc_[r][c][j] - m[r]);
                sc_[r][c][j] = e;
                s_ += e;
            }
#pragma unroll
        for (int o_ = 16; o_ > 0; o_ >>= 1)
            s_ += __shfl_xor_sync(0xffffffffu, s_, o_);
        sum[r] = s_;
    }
    if (lane == 0) {
#pragma unroll
        for (int r = 0; r < 4; r++) red[(tg * 4 + r) * 2 + w2] = sum[r];
    }
    __syncthreads();

#pragma unroll
    for (int r = 0; r < 4; r++) {
        const int row = tg * 4 + r;
        const float inv = 1.0f / (red[row * 2 + 0] + red[row * 2 + 1]);
        const int tglob = t0 + row;
        float* orow = &out[(((size_t)h * BSZ + b) * SEQ + tglob) * SEQ];
#pragma unroll
        for (int c = 0; c < NCH; c++)
#pragma unroll
            for (int j = 0; j < 8; j++)
                orow[c * SC + j * 64 + cl] = sc_[r][c][j] * inv;
    }
}

// ---------------------------------------------------------------------------
extern "C" void kernel_launch(void* const* d_in, const int* in_sizes, int n_in,
                              void* d_out, int out_size)
{
    const float* x    = (const float*)d_in[0];
    const float* pos  = (const float*)d_in[1];
    const float* off  = (const float*)d_in[2];
    const float* W    = (const float*)d_in[3];
    const float* bias = (const float*)d_in[4];
    float* out = (float*)d_out;

    cudaFuncSetAttribute(attn_kernel, cudaFuncAttributeMaxDynamicSharedMemorySize,
                         SM_FLOATS * (int)sizeof(float));

    dim3 gproj((IN_PROJ + 63) / 64, (SEQ * BSZ) / 64);   // 9 x 128
    proj_kernel<<<gproj, 256>>>(x, W, bias);

    dim3 gattn(SEQ / TT, NH, BSZ);                        // 64 x 8 x 8
    attn_kernel<<<gattn, 256, SM_FLOATS * (int)sizeof(float)>>>(pos, off, out);
}